// round 15
// baseline (speedup 1.0000x reference)
#include <cuda_runtime.h>
#include <cuda_bf16.h>
#include <cstdint>

#define NNODE 50000
#define NEDGE 800000

// ---------------- device scratch (allocation-free, 16B-aligned) ----------------
__device__ int   g_rowptr[NNODE + 1];
__device__ int   g_fill[NNODE];
__device__ int   g_col[NEDGE];
__device__ int   g_bsum[64];
__device__ float g_deginv[NNODE];
__device__ __align__(16) float          g_inp[(size_t)NNODE * 128];  // fp32 residual source
__device__ __align__(16) __nv_bfloat16  g_bufA[(size_t)NNODE * 128]; // hidden states (bf16)
__device__ __align__(16) __nv_bfloat16  g_bufB[(size_t)NNODE * 128];
__device__ __align__(16) float          g_aggf[(size_t)NNODE * 64];  // fp32 Nx64 p buffer
// packed bf16x2 pre-transposed weights: [n][k2] per layer
__device__ __align__(16) unsigned g_wbf[5 * 8192 + 2 * 4096];

__device__ __forceinline__ int clampN(int v) { return min(max(v, 0), NNODE - 1); }

__device__ __forceinline__ void mma_bf16(float* c, const unsigned* a, unsigned b0,
                                         unsigned b1) {
    asm volatile(
        "mma.sync.aligned.m16n8k16.row.col.f32.bf16.bf16.f32 "
        "{%0,%1,%2,%3}, {%4,%5,%6,%7}, {%8,%9}, {%0,%1,%2,%3};"
        : "+f"(c[0]), "+f"(c[1]), "+f"(c[2]), "+f"(c[3])
        : "r"(a[0]), "r"(a[1]), "r"(a[2]), "r"(a[3]), "r"(b0), "r"(b1));
}

// ---------------- weight pre-convert: fp32 [k][n] -> packed bf16x2 [n][k2] ----------------
__global__ void __launch_bounds__(256) k_wconv(
    const float* __restrict__ w_in, const float* __restrict__ w_l0,
    const float* __restrict__ w_r0, const float* __restrict__ w_l1,
    const float* __restrict__ w_r1, const float* __restrict__ w_l2,
    const float* __restrict__ w_r2) {
    int idx = blockIdx.x * 256 + threadIdx.x;
    const float* W;
    int OUTC, n, k2;
    unsigned* dst;
    if (idx < 40960) {                    // 5 layers of 128x128
        int L = idx >> 13;
        int r = idx & 8191;
        OUTC = 128;
        n = r & 127;
        k2 = r >> 7;
        W = (L == 0) ? w_in : (L == 1) ? w_l0 : (L == 2) ? w_r0 : (L == 3) ? w_l1 : w_r1;
        dst = g_wbf + L * 8192 + n * 64 + k2;
    } else if (idx < 49152) {             // 2 layers of 128x64
        int r = idx - 40960;
        int L = r >> 12;
        r &= 4095;
        OUTC = 64;
        n = r & 63;
        k2 = r >> 6;
        W = L ? w_r2 : w_l2;
        dst = g_wbf + 40960 + L * 4096 + n * 64 + k2;
    } else {
        return;
    }
    __nv_bfloat162 p = __floats2bfloat162_rn(W[(size_t)(2 * k2) * OUTC + n],
                                             W[(size_t)(2 * k2 + 1) * OUTC + n]);
    *dst = *reinterpret_cast<unsigned*>(&p);
}

// ---------------- CSR build ----------------
__global__ void k_zero_fill() {
    int i = blockIdx.x * blockDim.x + threadIdx.x;
    if (i < NNODE) g_fill[i] = 0;
}

__global__ void k_hist(const int* __restrict__ ei) {
    int q = blockIdx.x * blockDim.x + threadIdx.x;
    if (q < NEDGE / 4) {
        int4 d = ((const int4*)(ei + NEDGE))[q];
        atomicAdd(&g_fill[clampN(d.x)], 1);
        atomicAdd(&g_fill[clampN(d.y)], 1);
        atomicAdd(&g_fill[clampN(d.z)], 1);
        atomicAdd(&g_fill[clampN(d.w)], 1);
    }
}

__global__ void __launch_bounds__(1024) k_scan1() {
    const int t = threadIdx.x;
    const int i = blockIdx.x * 1024 + t;
    __shared__ int wsum[32];
    int v = (i < NNODE) ? g_fill[i] : 0;
    int inc = v;
#pragma unroll
    for (int o = 1; o < 32; o <<= 1) {
        int y = __shfl_up_sync(0xffffffffu, inc, o);
        if ((t & 31) >= o) inc += y;
    }
    if ((t & 31) == 31) wsum[t >> 5] = inc;
    __syncthreads();
    if (t < 32) {
        int wv = wsum[t];
        int winc = wv;
#pragma unroll
        for (int o = 1; o < 32; o <<= 1) {
            int y = __shfl_up_sync(0xffffffffu, winc, o);
            if (t >= o) winc += y;
        }
        wsum[t] = winc - wv;
    }
    __syncthreads();
    int excl = inc - v + wsum[t >> 5];
    if (i < NNODE) g_rowptr[i] = excl;
    if (t == 1023) g_bsum[blockIdx.x] = excl + v;
}

// scan3 with inlined block-sum prefix
__global__ void __launch_bounds__(1024) k_scan3() {
    __shared__ int base_sh;
    const int t = threadIdx.x;
    if (t < 32) {
        int b = blockIdx.x;
        int s = ((t < b) ? g_bsum[t] : 0) + ((t + 32 < b) ? g_bsum[t + 32] : 0);
#pragma unroll
        for (int o = 16; o; o >>= 1) s += __shfl_xor_sync(0xffffffffu, s, o);
        if (t == 0) base_sh = s;
    }
    __syncthreads();
    const int i = blockIdx.x * 1024 + t;
    if (i < NNODE) {
        int excl = g_rowptr[i] + base_sh;
        int v = g_fill[i];
        g_rowptr[i] = excl;
        g_fill[i]   = excl;
        g_deginv[i] = 1.0f / (float)max(v, 1);
        if (i == 0) g_rowptr[NNODE] = NEDGE;
    }
}

__global__ void k_csr_fill(const int* __restrict__ ei) {
    int q = blockIdx.x * blockDim.x + threadIdx.x;
    if (q < NEDGE / 4) {
        int4 s = ((const int4*)ei)[q];
        int4 d = ((const int4*)(ei + NEDGE))[q];
        int p;
        p = atomicAdd(&g_fill[clampN(d.x)], 1); if ((unsigned)p < NEDGE) g_col[p] = clampN(s.x);
        p = atomicAdd(&g_fill[clampN(d.y)], 1); if ((unsigned)p < NEDGE) g_col[p] = clampN(s.y);
        p = atomicAdd(&g_fill[clampN(d.z)], 1); if ((unsigned)p < NEDGE) g_col[p] = clampN(s.z);
        p = atomicAdd(&g_fill[clampN(d.w)], 1); if ((unsigned)p < NEDGE) g_col[p] = clampN(s.w);
    }
}

// ---------------- fused bf16 GEMM (+ in-prologue mean aggregation for MODE 1) ----------
// ASu: [128][68] full-K A tile (bf16x2 per u32); Wn: [OUTC][68] packed weights.
// Banks of frag reads: (4*tg4 + t4) -> conflict-free.
// MODE 0: A=x (fp32->bf16); K=128; g_inp=v (fp32), g_bufA=relu(v)
// MODE 1: phase1 A=gather-mean(h), W=W_l; phase2 A=h, W=W_r (K=256 total);
//         out(sel)=relu(v)+0.2*g_inp
// MODE 2: A=h(bufA); dual W (w_l2|w_r2); p->g_aggf, q=+b -> outExt
template <int OUTC>
__device__ __forceinline__ void load_Wq(unsigned (*Wn)[68], const unsigned* __restrict__ Wp,
                                        int t) {
    for (int i = t; i < OUTC * 16; i += 256) {
        int n = i >> 4, j = i & 15;
        uint4 v = *((const uint4*)(Wp + n * 64) + j);
        *((uint4*)(&Wn[n][0]) + j) = v;
    }
}

template <int OUTC, int MODE>
__global__ void __launch_bounds__(256) k_mma(
    const float* __restrict__ Aext, int w1off, int w2off,
    const float* __restrict__ bias, float* __restrict__ outExt, int sel) {
    constexpr int WARPS_N = OUTC / 32;       // 4 (M0/M1) or 2 (M2)
    constexpr int WARPS_M = 8 / WARPS_N;     // 2 or 4
    constexpr int MT = 128 / (WARPS_M * 16); // 4 or 2

    extern __shared__ __align__(16) unsigned shm[];
    unsigned (*ASu)[68] = (unsigned(*)[68])shm;
    unsigned (*Wn0)[68] = (unsigned(*)[68])(shm + 128 * 68);
    unsigned (*Wn1)[68] = (unsigned(*)[68])(shm + 128 * 68 + 64 * 68); // MODE2 only

    const int t    = threadIdx.x;
    const int lane = t & 31;
    const int wid  = t >> 5;
    const int wm   = wid / WARPS_N;
    const int wn   = wid % WARPS_N;
    const int mBase = wm * (MT * 16);
    const int nBase = wn * 32;
    const int row0  = blockIdx.x * 128;
    const int tg4   = lane >> 2;
    const int t4    = lane & 3;

    const unsigned* W1p = g_wbf + w1off;
    const unsigned* W2p = g_wbf + w2off;

    const __nv_bfloat16* hsrc =
        (MODE == 1) ? (sel ? g_bufB : g_bufA) : g_bufA;   // MODE2 uses g_bufA
    __nv_bfloat16* outb = nullptr;
    if (MODE == 0) outb = g_bufA;
    else if (MODE == 1) outb = sel ? g_bufA : g_bufB;

    float acc[MT][4][4];
    float acc2[(MODE == 2) ? MT : 1][(MODE == 2) ? 4 : 1][(MODE == 2) ? 4 : 1];
#pragma unroll
    for (int mt = 0; mt < MT; mt++)
#pragma unroll
        for (int nt = 0; nt < 4; nt++)
#pragma unroll
            for (int i = 0; i < 4; i++) {
                acc[mt][nt][i] = 0.f;
                if constexpr (MODE == 2) acc2[mt][nt][i] = 0.f;
            }

    // ---- A loaders ----
    auto load_h = [&]() {   // bf16 rows -> ASu (uint4 stores, 16B-aligned: 68r+4j ≡ 0 mod 4)
        for (int idx = t; idx < 128 * 16; idx += 256) {
            int r = idx >> 4, j = idx & 15;
            int gr = row0 + r;
            uint4 v = (gr < NNODE)
                ? *(const uint4*)(hsrc + (size_t)gr * 128 + j * 8)
                : make_uint4(0u, 0u, 0u, 0u);
            *((uint4*)(&ASu[r][0]) + j) = v;
        }
    };
    auto gather_agg = [&]() {   // warp-per-node mean aggregation -> ASu
        for (int n = wid; n < 128; n += 8) {
            int node = row0 + n;
            float ax = 0.f, ay = 0.f, az = 0.f, aw = 0.f;
            float bx = 0.f, by = 0.f, bz = 0.f, bw = 0.f;
            if (node < NNODE) {
                int beg = g_rowptr[node], end = g_rowptr[node + 1];
                int i = beg;
                for (; i + 3 < end; i += 4) {   // 4 independent load legs
                    int s0 = g_col[i], s1 = g_col[i + 1];
                    int s2 = g_col[i + 2], s3 = g_col[i + 3];
                    uint2 r0 = __ldg((const uint2*)(hsrc + (size_t)s0 * 128 + lane * 4));
                    uint2 r1 = __ldg((const uint2*)(hsrc + (size_t)s1 * 128 + lane * 4));
                    uint2 r2 = __ldg((const uint2*)(hsrc + (size_t)s2 * 128 + lane * 4));
                    uint2 r3 = __ldg((const uint2*)(hsrc + (size_t)s3 * 128 + lane * 4));
                    float2 f;
                    f = __bfloat1622float2(*reinterpret_cast<__nv_bfloat162*>(&r0.x)); ax += f.x; ay += f.y;
                    f = __bfloat1622float2(*reinterpret_cast<__nv_bfloat162*>(&r0.y)); az += f.x; aw += f.y;
                    f = __bfloat1622float2(*reinterpret_cast<__nv_bfloat162*>(&r1.x)); bx += f.x; by += f.y;
                    f = __bfloat1622float2(*reinterpret_cast<__nv_bfloat162*>(&r1.y)); bz += f.x; bw += f.y;
                    f = __bfloat1622float2(*reinterpret_cast<__nv_bfloat162*>(&r2.x)); ax += f.x; ay += f.y;
                    f = __bfloat1622float2(*reinterpret_cast<__nv_bfloat162*>(&r2.y)); az += f.x; aw += f.y;
                    f = __bfloat1622float2(*reinterpret_cast<__nv_bfloat162*>(&r3.x)); bx += f.x; by += f.y;
                    f = __bfloat1622float2(*reinterpret_cast<__nv_bfloat162*>(&r3.y)); bz += f.x; bw += f.y;
                }
                for (; i < end; i++) {
                    int s0 = g_col[i];
                    uint2 r0 = __ldg((const uint2*)(hsrc + (size_t)s0 * 128 + lane * 4));
                    float2 f;
                    f = __bfloat1622float2(*reinterpret_cast<__nv_bfloat162*>(&r0.x)); ax += f.x; ay += f.y;
                    f = __bfloat1622float2(*reinterpret_cast<__nv_bfloat162*>(&r0.y)); az += f.x; aw += f.y;
                }
                float dg = g_deginv[node];
                ax = (ax + bx) * dg; ay = (ay + by) * dg;
                az = (az + bz) * dg; aw = (aw + bw) * dg;
            }
            __nv_bfloat162 p0 = __floats2bfloat162_rn(ax, ay);
            __nv_bfloat162 p1 = __floats2bfloat162_rn(az, aw);
            ASu[n][2 * lane]     = *reinterpret_cast<unsigned*>(&p0);
            ASu[n][2 * lane + 1] = *reinterpret_cast<unsigned*>(&p1);
        }
    };
    auto load_x = [&]() {   // fp32 ext rows -> bf16 ASu
        for (int idx = t; idx < 128 * 64; idx += 256) {
            int r = idx >> 6, k2 = idx & 63;
            int gr = row0 + r;
            float2 f = (gr < NNODE)
                ? *(const float2*)(Aext + (size_t)gr * 128 + 2 * k2)
                : make_float2(0.f, 0.f);
            __nv_bfloat162 p = __floats2bfloat162_rn(f.x, f.y);
            ASu[r][k2] = *reinterpret_cast<unsigned*>(&p);
        }
    };

    auto mma_chunk = [&](int kc4) {
#pragma unroll
        for (int ks = 0; ks < 2; ks++) {
            int kb = kc4 * 16 + ks * 8;
            unsigned a[MT][4];
#pragma unroll
            for (int mt = 0; mt < MT; mt++) {
                int r = mBase + mt * 16 + tg4;
                a[mt][0] = ASu[r][kb + t4];
                a[mt][1] = ASu[r + 8][kb + t4];
                a[mt][2] = ASu[r][kb + 4 + t4];
                a[mt][3] = ASu[r + 8][kb + 4 + t4];
            }
#pragma unroll
            for (int nt = 0; nt < 4; nt++) {
                int cn = nBase + nt * 8 + tg4;
                unsigned b0 = Wn0[cn][kb + t4];
                unsigned b1 = Wn0[cn][kb + 4 + t4];
#pragma unroll
                for (int mt = 0; mt < MT; mt++) mma_bf16(acc[mt][nt], a[mt], b0, b1);
                if constexpr (MODE == 2) {
                    unsigned d0 = Wn1[cn][kb + t4];
                    unsigned d1 = Wn1[cn][kb + 4 + t4];
#pragma unroll
                    for (int mt = 0; mt < MT; mt++) mma_bf16(acc2[mt][nt], a[mt], d0, d1);
                }
            }
        }
    };

    if constexpr (MODE == 0) {
        load_x();
        load_Wq<OUTC>(Wn0, W1p, t);
        __syncthreads();
#pragma unroll
        for (int c = 0; c < 4; c++) mma_chunk(c);
    } else if constexpr (MODE == 1) {
        gather_agg();
        load_Wq<OUTC>(Wn0, W1p, t);
        __syncthreads();
#pragma unroll
        for (int c = 0; c < 4; c++) mma_chunk(c);
        __syncthreads();
        load_h();
        load_Wq<OUTC>(Wn0, W2p, t);
        __syncthreads();
#pragma unroll
        for (int c = 0; c < 4; c++) mma_chunk(c);
    } else {
        load_h();
        load_Wq<64>(Wn0, W1p, t);
        load_Wq<64>(Wn1, W2p, t);
        __syncthreads();
#pragma unroll
        for (int c = 0; c < 4; c++) mma_chunk(c);
    }

    // ---- epilogue ----
#pragma unroll
    for (int mt = 0; mt < MT; mt++) {
#pragma unroll
        for (int nt = 0; nt < 4; nt++) {
            int gc = nBase + nt * 8 + 2 * t4;
            float b0 = bias ? bias[gc] : 0.f;
            float b1 = bias ? bias[gc + 1] : 0.f;
#pragma unroll
            for (int half = 0; half < 2; half++) {
                int gr = row0 + mBase + mt * 16 + tg4 + half * 8;
                if (gr >= NNODE) continue;
                float v0 = acc[mt][nt][half * 2];
                float v1 = acc[mt][nt][half * 2 + 1];
                size_t o = (size_t)gr * OUTC + gc;
                if constexpr (MODE == 0) {
                    v0 += b0; v1 += b1;
                    *(float2*)(g_inp + o) = make_float2(v0, v1);
                    __nv_bfloat162 h2 =
                        __floats2bfloat162_rn(fmaxf(v0, 0.f), fmaxf(v1, 0.f));
                    *(__nv_bfloat162*)(outb + o) = h2;
                } else if constexpr (MODE == 1) {
                    v0 += b0; v1 += b1;
                    float2 rin = *(const float2*)(g_inp + o);
                    __nv_bfloat162 h2 = __floats2bfloat162_rn(
                        fmaxf(v0, 0.f) + 0.2f * rin.x, fmaxf(v1, 0.f) + 0.2f * rin.y);
                    *(__nv_bfloat162*)(outb + o) = h2;
                } else {
                    *(float2*)(g_aggf + o) = make_float2(v0, v1);   // p (fp32)
                    float q0 = acc2[mt][nt][half * 2] + b0;
                    float q1 = acc2[mt][nt][half * 2 + 1] + b1;
                    *(float2*)(outExt + o) = make_float2(q0, q1);
                }
            }
        }
    }
}

// ---------------- final: mean-agg of p (64-dim fp32) + q, fused log_softmax ------------
__global__ void __launch_bounds__(256) k_agg64_lsm(float* __restrict__ out) {
    int w = (blockIdx.x * blockDim.x + threadIdx.x) >> 5;
    if (w >= NNODE) return;
    const float* __restrict__ p = g_aggf;
    int lane = threadIdx.x & 31;
    int beg = g_rowptr[w], end = g_rowptr[w + 1];
    float ax = 0.f, ay = 0.f;
    int i = beg;
    for (; i + 3 < end; i += 4) {
        int s0 = g_col[i], s1 = g_col[i + 1], s2 = g_col[i + 2], s3 = g_col[i + 3];
        float2 a = __ldg((const float2*)(p + (size_t)s0 * 64 + lane * 2));
        float2 b = __ldg((const float2*)(p + (size_t)s1 * 64 + lane * 2));
        float2 cc = __ldg((const float2*)(p + (size_t)s2 * 64 + lane * 2));
        float2 d = __ldg((const float2*)(p + (size_t)s3 * 64 + lane * 2));
        ax += (a.x + b.x) + (cc.x + d.x);
        ay += (a.y + b.y) + (cc.y + d.y);
    }
    for (; i < end; i++) {
        int s0 = g_col[i];
        float2 a = __ldg((const float2*)(p + (size_t)s0 * 64 + lane * 2));
        ax += a.x; ay += a.y;
    }
    float d = g_deginv[w];
    float2 q = *(float2*)(out + (size_t)w * 64 + lane * 2);
    float v0 = q.x + ax * d;
    float v1 = q.y + ay * d;
    float m = fmaxf(v0, v1);
#pragma unroll
    for (int s = 16; s; s >>= 1) m = fmaxf(m, __shfl_xor_sync(0xffffffffu, m, s));
    float e = expf(v0 - m) + expf(v1 - m);
#pragma unroll
    for (int s = 16; s; s >>= 1) e += __shfl_xor_sync(0xffffffffu, e, s);
    float l = m + logf(e);
    *(float2*)(out + (size_t)w * 64 + lane * 2) = make_float2(v0 - l, v1 - l);
}

// ---------------- launcher (kernel launches + event fork/join — graph-capture safe) ----
extern "C" void kernel_launch(void* const* d_in, const int* in_sizes, int n_in,
                              void* d_out, int out_size) {
    const float* x    = (const float*)d_in[0];
    const int*   ei   = (const int*)d_in[1];     // int32 (JAX demotes int64)
    const float* w_in = (const float*)d_in[2];
    const float* b_in = (const float*)d_in[3];
    const float* w_l0 = (const float*)d_in[4];
    const float* w_r0 = (const float*)d_in[5];
    const float* b0   = (const float*)d_in[6];
    const float* w_l1 = (const float*)d_in[7];
    const float* w_r1 = (const float*)d_in[8];
    const float* b1   = (const float*)d_in[9];
    const float* w_l2 = (const float*)d_in[10];
    const float* w_r2 = (const float*)d_in[11];
    const float* b2   = (const float*)d_in[12];
    float* out = (float*)d_out;

    const int GB128 = (NNODE + 127) / 128;           // 391
    const int EDGE4_BLOCKS = (NEDGE / 4 + 255) / 256;
    const int WARP_BLOCKS = (NNODE * 32 + 255) / 256;
    const int SCAN_BLOCKS = (NNODE + 1023) / 1024;   // 49

    const int W_IN = 0, W_L0 = 8192, W_R0 = 16384, W_L1 = 24576, W_R1 = 32768;
    const int W_L2 = 40960, W_R2 = 45056;
    const int SMEM = (128 + 64 + 64) * 68 * 4;       // 69632 B, uniform all modes

    // one-time host-side resources (created on the FIRST call, which is NOT captured)
    static cudaStream_t sCsr = nullptr;
    static cudaEvent_t evFork = nullptr, evJoin = nullptr;
    if (!sCsr) {
        cudaStreamCreateWithFlags(&sCsr, cudaStreamNonBlocking);
        cudaEventCreateWithFlags(&evFork, cudaEventDisableTiming);
        cudaEventCreateWithFlags(&evJoin, cudaEventDisableTiming);
        cudaFuncSetAttribute(k_mma<128, 0>, cudaFuncAttributeMaxDynamicSharedMemorySize, SMEM);
        cudaFuncSetAttribute(k_mma<128, 1>, cudaFuncAttributeMaxDynamicSharedMemorySize, SMEM);
        cudaFuncSetAttribute(k_mma<64, 2>,  cudaFuncAttributeMaxDynamicSharedMemorySize, SMEM);
    }

    // ---- fork: CSR branch runs concurrently with wconv + embedding GEMM ----
    cudaEventRecord(evFork, 0);
    cudaStreamWaitEvent(sCsr, evFork, 0);

    // CSR branch (stream sCsr)
    k_zero_fill<<<(NNODE + 255) / 256, 256, 0, sCsr>>>();
    k_hist<<<EDGE4_BLOCKS, 256, 0, sCsr>>>(ei);
    k_scan1<<<SCAN_BLOCKS, 1024, 0, sCsr>>>();
    k_scan3<<<SCAN_BLOCKS, 1024, 0, sCsr>>>();
    k_csr_fill<<<EDGE4_BLOCKS, 256, 0, sCsr>>>(ei);
    cudaEventRecord(evJoin, sCsr);

    // main branch (capture stream): weights + input embedding
    k_wconv<<<192, 256>>>(w_in, w_l0, w_r0, w_l1, w_r1, w_l2, w_r2);
    k_mma<128, 0><<<GB128, 256, SMEM>>>(x, W_IN, 0, b_in, nullptr, 0);

    // ---- join: fused agg+GEMM needs both CSR and embedding ----
    cudaStreamWaitEvent(0, evJoin, 0);

    // layer 0: fused [mean-agg(bufA) | bufA] GEMM -> bufB
    k_mma<128, 1><<<GB128, 256, SMEM>>>(nullptr, W_L0, W_R0, b0, nullptr, 0);
    // layer 1: fused [mean-agg(bufB) | bufB] GEMM -> bufA
    k_mma<128, 1><<<GB128, 256, SMEM>>>(nullptr, W_L1, W_R1, b1, nullptr, 1);
    // layer 2: p = bufA@w_l2 -> g_aggf; q = bufA@w_r2 + b2 -> out
    k_mma<64, 2><<<GB128, 256, SMEM>>>(nullptr, W_L2, W_R2, b2, out, 0);
    // out = log_softmax(q + mean_agg(p))
    k_agg64_lsm<<<WARP_BLOCKS, 256>>>(out);
}

// round 17
// speedup vs baseline: 1.3603x; 1.3603x over previous
#include <cuda_runtime.h>
#include <cuda_bf16.h>
#include <cstdint>

#define NNODE 50000
#define NEDGE 800000

// ---------------- device scratch (allocation-free, 16B-aligned) ----------------
__device__ int   g_rowptr[NNODE + 1];
__device__ int   g_fill[NNODE];
__device__ int   g_col[NEDGE];
__device__ int   g_bsum[64];
__device__ float g_deginv[NNODE];
__device__ __align__(16) float          g_inp[(size_t)NNODE * 128];  // fp32 residual source
__device__ __align__(16) __nv_bfloat16  g_bufA[(size_t)NNODE * 128]; // hidden states (bf16)
__device__ __align__(16) __nv_bfloat16  g_bufB[(size_t)NNODE * 128];
__device__ __align__(16) float          g_aggf[(size_t)NNODE * 128]; // bf16 agg OR fp32 Nx64 p
// packed bf16x2 pre-transposed weights: [n][k2] per layer
__device__ __align__(16) unsigned g_wbf[5 * 8192 + 2 * 4096];

__device__ __forceinline__ int clampN(int v) { return min(max(v, 0), NNODE - 1); }

__device__ __forceinline__ void mma_bf16(float* c, const unsigned* a, unsigned b0,
                                         unsigned b1) {
    asm volatile(
        "mma.sync.aligned.m16n8k16.row.col.f32.bf16.bf16.f32 "
        "{%0,%1,%2,%3}, {%4,%5,%6,%7}, {%8,%9}, {%0,%1,%2,%3};"
        : "+f"(c[0]), "+f"(c[1]), "+f"(c[2]), "+f"(c[3])
        : "r"(a[0]), "r"(a[1]), "r"(a[2]), "r"(a[3]), "r"(b0), "r"(b1));
}

// ---------------- weight pre-convert: fp32 [k][n] -> packed bf16x2 [n][k2] ----------------
__global__ void __launch_bounds__(256) k_wconv(
    const float* __restrict__ w_in, const float* __restrict__ w_l0,
    const float* __restrict__ w_r0, const float* __restrict__ w_l1,
    const float* __restrict__ w_r1, const float* __restrict__ w_l2,
    const float* __restrict__ w_r2) {
    int idx = blockIdx.x * 256 + threadIdx.x;
    const float* W;
    int OUTC, n, k2;
    unsigned* dst;
    if (idx < 40960) {                    // 5 layers of 128x128
        int L = idx >> 13;
        int r = idx & 8191;
        OUTC = 128;
        n = r & 127;
        k2 = r >> 7;
        W = (L == 0) ? w_in : (L == 1) ? w_l0 : (L == 2) ? w_r0 : (L == 3) ? w_l1 : w_r1;
        dst = g_wbf + L * 8192 + n * 64 + k2;
    } else if (idx < 49152) {             // 2 layers of 128x64
        int r = idx - 40960;
        int L = r >> 12;
        r &= 4095;
        OUTC = 64;
        n = r & 63;
        k2 = r >> 6;
        W = L ? w_r2 : w_l2;
        dst = g_wbf + 40960 + L * 4096 + n * 64 + k2;
    } else {
        return;
    }
    __nv_bfloat162 p = __floats2bfloat162_rn(W[(size_t)(2 * k2) * OUTC + n],
                                             W[(size_t)(2 * k2 + 1) * OUTC + n]);
    *dst = *reinterpret_cast<unsigned*>(&p);
}

// ---------------- CSR build ----------------
__global__ void k_zero_fill() {
    int i = blockIdx.x * blockDim.x + threadIdx.x;
    if (i < NNODE) g_fill[i] = 0;
}

__global__ void k_hist(const int* __restrict__ ei) {
    int q = blockIdx.x * blockDim.x + threadIdx.x;
    if (q < NEDGE / 4) {
        int4 d = ((const int4*)(ei + NEDGE))[q];
        atomicAdd(&g_fill[clampN(d.x)], 1);
        atomicAdd(&g_fill[clampN(d.y)], 1);
        atomicAdd(&g_fill[clampN(d.z)], 1);
        atomicAdd(&g_fill[clampN(d.w)], 1);
    }
}

__global__ void __launch_bounds__(1024) k_scan1() {
    const int t = threadIdx.x;
    const int i = blockIdx.x * 1024 + t;
    __shared__ int wsum[32];
    int v = (i < NNODE) ? g_fill[i] : 0;
    int inc = v;
#pragma unroll
    for (int o = 1; o < 32; o <<= 1) {
        int y = __shfl_up_sync(0xffffffffu, inc, o);
        if ((t & 31) >= o) inc += y;
    }
    if ((t & 31) == 31) wsum[t >> 5] = inc;
    __syncthreads();
    if (t < 32) {
        int wv = wsum[t];
        int winc = wv;
#pragma unroll
        for (int o = 1; o < 32; o <<= 1) {
            int y = __shfl_up_sync(0xffffffffu, winc, o);
            if (t >= o) winc += y;
        }
        wsum[t] = winc - wv;
    }
    __syncthreads();
    int excl = inc - v + wsum[t >> 5];
    if (i < NNODE) g_rowptr[i] = excl;
    if (t == 1023) g_bsum[blockIdx.x] = excl + v;
}

// scan3 with inlined block-sum prefix (no inter-block spin; plain barrier chain)
__global__ void __launch_bounds__(1024) k_scan3() {
    __shared__ int base_sh;
    const int t = threadIdx.x;
    if (t < 32) {
        int b = blockIdx.x;
        int s = ((t < b) ? g_bsum[t] : 0) + ((t + 32 < b) ? g_bsum[t + 32] : 0);
#pragma unroll
        for (int o = 16; o; o >>= 1) s += __shfl_xor_sync(0xffffffffu, s, o);
        if (t == 0) base_sh = s;
    }
    __syncthreads();
    const int i = blockIdx.x * 1024 + t;
    if (i < NNODE) {
        int excl = g_rowptr[i] + base_sh;
        int v = g_fill[i];
        g_rowptr[i] = excl;
        g_fill[i]   = excl;
        g_deginv[i] = 1.0f / (float)max(v, 1);
        if (i == 0) g_rowptr[NNODE] = NEDGE;
    }
}

__global__ void k_csr_fill(const int* __restrict__ ei) {
    int q = blockIdx.x * blockDim.x + threadIdx.x;
    if (q < NEDGE / 4) {
        int4 s = ((const int4*)ei)[q];
        int4 d = ((const int4*)(ei + NEDGE))[q];
        int p;
        p = atomicAdd(&g_fill[clampN(d.x)], 1); if ((unsigned)p < NEDGE) g_col[p] = clampN(s.x);
        p = atomicAdd(&g_fill[clampN(d.y)], 1); if ((unsigned)p < NEDGE) g_col[p] = clampN(s.y);
        p = atomicAdd(&g_fill[clampN(d.z)], 1); if ((unsigned)p < NEDGE) g_col[p] = clampN(s.z);
        p = atomicAdd(&g_fill[clampN(d.w)], 1); if ((unsigned)p < NEDGE) g_col[p] = clampN(s.w);
    }
}

// ---------------- mean aggregation (128-dim, bf16): warp/node, x4 unroll ----------------
__global__ void __launch_bounds__(256) k_agg(int sel) {
    int w = (blockIdx.x * blockDim.x + threadIdx.x) >> 5;
    if (w >= NNODE) return;
    const __nv_bfloat16* __restrict__ src = sel ? g_bufB : g_bufA;
    int lane = threadIdx.x & 31;
    int beg = g_rowptr[w], end = g_rowptr[w + 1];
    float ax = 0.f, ay = 0.f, az = 0.f, aw = 0.f;
    int i = beg;
    for (; i + 3 < end; i += 4) {
        int s0 = g_col[i], s1 = g_col[i + 1], s2 = g_col[i + 2], s3 = g_col[i + 3];
#pragma unroll
        for (int u = 0; u < 4; u++) {
            int sn = (u == 0) ? s0 : (u == 1) ? s1 : (u == 2) ? s2 : s3;
            uint2 raw = __ldg((const uint2*)(src + (size_t)sn * 128 + lane * 4));
            float2 f0 = __bfloat1622float2(*reinterpret_cast<__nv_bfloat162*>(&raw.x));
            float2 f1 = __bfloat1622float2(*reinterpret_cast<__nv_bfloat162*>(&raw.y));
            ax += f0.x; ay += f0.y; az += f1.x; aw += f1.y;
        }
    }
    for (; i < end; i++) {
        int sn = g_col[i];
        uint2 raw = __ldg((const uint2*)(src + (size_t)sn * 128 + lane * 4));
        float2 f0 = __bfloat1622float2(*reinterpret_cast<__nv_bfloat162*>(&raw.x));
        float2 f1 = __bfloat1622float2(*reinterpret_cast<__nv_bfloat162*>(&raw.y));
        ax += f0.x; ay += f0.y; az += f1.x; aw += f1.y;
    }
    float d = g_deginv[w];
    __nv_bfloat16* dst = (__nv_bfloat16*)g_aggf;
    __nv_bfloat162 o0 = __floats2bfloat162_rn(ax * d, ay * d);
    __nv_bfloat162 o1 = __floats2bfloat162_rn(az * d, aw * d);
    uint2 o;
    o.x = *reinterpret_cast<unsigned*>(&o0);
    o.y = *reinterpret_cast<unsigned*>(&o1);
    *(uint2*)(dst + (size_t)w * 128 + lane * 4) = o;
}

// ---------------- bf16 mma.sync GEMM: BM=128 tiles, resident packed weights ------------
template <int OUTC>
__device__ __forceinline__ void load_Wq(unsigned (*Wn)[68], const unsigned* __restrict__ Wp,
                                        int t) {
    for (int i = t; i < OUTC * 16; i += 256) {
        int n = i >> 4, j = i & 15;
        uint4 v = *((const uint4*)(Wp + n * 64) + j);
        *((uint4*)(&Wn[n][0]) + j) = v;
    }
}

template <int OUTC, int MODE>
__global__ void __launch_bounds__(256) k_mma(
    const float* __restrict__ Aext, int w1off, int w2off,
    const float* __restrict__ bias, float* __restrict__ outExt, int sel) {
    constexpr int BM = 128;
    constexpr int WARPS_N = OUTC / 32;
    constexpr int WARPS_M = 8 / WARPS_N;
    constexpr int MT = BM / (WARPS_M * 16);
    constexpr int NWB = (MODE == 2) ? 2 : 1;
    constexpr int NCH = (MODE == 1) ? 8 : 4;
    constexpr int PF  = BM / 16;

    __shared__ __align__(16) unsigned Wn[NWB][OUTC][68];
    __shared__ __align__(16) unsigned As[BM][20];

    const int t    = threadIdx.x;
    const int lane = t & 31;
    const int wid  = t >> 5;
    const int wm   = wid / WARPS_N;
    const int wn   = wid % WARPS_N;
    const int mBase = wm * (MT * 16);
    const int nBase = wn * 32;
    const int row0  = blockIdx.x * BM;
    const int tg4   = lane >> 2;
    const int t4    = lane & 3;

    const unsigned* W1p = g_wbf + w1off;
    const unsigned* W2p = g_wbf + w2off;

    const __nv_bfloat16* srcs[2] = {nullptr, nullptr};
    if (MODE == 1) {
        srcs[0] = (const __nv_bfloat16*)g_aggf;
        srcs[1] = sel ? g_bufB : g_bufA;
    } else if (MODE == 2) {
        srcs[0] = g_bufA;
    }
    __nv_bfloat16* outb = nullptr;
    if (MODE == 0) outb = g_bufA;
    else if (MODE == 1) outb = sel ? g_bufA : g_bufB;

    float acc[MT][4][4];
    float acc2[(MODE == 2) ? MT : 1][(MODE == 2) ? 4 : 1][(MODE == 2) ? 4 : 1];
#pragma unroll
    for (int mt = 0; mt < MT; mt++)
#pragma unroll
        for (int nt = 0; nt < 4; nt++)
#pragma unroll
            for (int i = 0; i < 4; i++) {
                acc[mt][nt][i] = 0.f;
                if constexpr (MODE == 2) acc2[mt][nt][i] = 0.f;
            }

    unsigned pf[PF];
    float2   pf2[(MODE == 0) ? PF : 1];

    auto prefetch = [&](int c) {
#pragma unroll
        for (int i = 0; i < PF; i++) {
            int idx = t + i * 256;
            int r = idx >> 4, k2 = idx & 15;
            int gr = row0 + r;
            if constexpr (MODE == 0) {
                pf2[i] = (gr < NNODE)
                    ? *(const float2*)(Aext + (size_t)gr * 128 + c * 32 + 2 * k2)
                    : make_float2(0.f, 0.f);
            } else {
                const __nv_bfloat16* A = (MODE == 1 && c >= 4) ? srcs[1] : srcs[0];
                int kc = (MODE == 1) ? (c & 3) : c;
                pf[i] = (gr < NNODE)
                    ? *(const unsigned*)(A + (size_t)gr * 128 + kc * 32 + 2 * k2)
                    : 0u;
            }
        }
    };
    auto store_tile = [&]() {
#pragma unroll
        for (int i = 0; i < PF; i++) {
            int idx = t + i * 256;
            int r = idx >> 4, k2 = idx & 15;
            if constexpr (MODE == 0) {
                __nv_bfloat162 p = __floats2bfloat162_rn(pf2[i].x, pf2[i].y);
                As[r][k2] = *reinterpret_cast<unsigned*>(&p);
            } else {
                As[r][k2] = pf[i];
            }
        }
    };
    auto mma_chunk = [&](int kc4) {
#pragma unroll
        for (int ks = 0; ks < 2; ks++) {
            int kb = ks * 8;
            unsigned a[MT][4];
#pragma unroll
            for (int mt = 0; mt < MT; mt++) {
                int r = mBase + mt * 16 + tg4;
                a[mt][0] = As[r][kb + t4];
                a[mt][1] = As[r + 8][kb + t4];
                a[mt][2] = As[r][kb + 4 + t4];
                a[mt][3] = As[r + 8][kb + 4 + t4];
            }
            int wk = kc4 * 16 + kb;
#pragma unroll
            for (int nt = 0; nt < 4; nt++) {
                int cn = nBase + nt * 8 + tg4;
                unsigned b0 = Wn[0][cn][wk + t4];
                unsigned b1 = Wn[0][cn][wk + 4 + t4];
#pragma unroll
                for (int mt = 0; mt < MT; mt++) mma_bf16(acc[mt][nt], a[mt], b0, b1);
                if constexpr (MODE == 2) {
                    unsigned d0 = Wn[1][cn][wk + t4];
                    unsigned d1 = Wn[1][cn][wk + 4 + t4];
#pragma unroll
                    for (int mt = 0; mt < MT; mt++) mma_bf16(acc2[mt][nt], a[mt], d0, d1);
                }
            }
        }
    };

    load_Wq<OUTC>(Wn[0], W1p, t);
    if constexpr (MODE == 2) load_Wq<OUTC>(Wn[1], W2p, t);
    prefetch(0);
    for (int c = 0; c < NCH; c++) {
        store_tile();
        __syncthreads();
        if (c + 1 < NCH) prefetch(c + 1);
        mma_chunk((MODE == 1) ? (c & 3) : c);
        __syncthreads();
        if (MODE == 1 && c == 3) load_Wq<OUTC>(Wn[0], W2p, t);  // fenced by next chunk's sync
    }

    // ---- epilogue ----
#pragma unroll
    for (int mt = 0; mt < MT; mt++) {
#pragma unroll
        for (int nt = 0; nt < 4; nt++) {
            int gc = nBase + nt * 8 + 2 * t4;
            float b0 = bias ? bias[gc] : 0.f;
            float b1 = bias ? bias[gc + 1] : 0.f;
#pragma unroll
            for (int half = 0; half < 2; half++) {
                int gr = row0 + mBase + mt * 16 + tg4 + half * 8;
                if (gr >= NNODE) continue;
                float v0 = acc[mt][nt][half * 2];
                float v1 = acc[mt][nt][half * 2 + 1];
                size_t o = (size_t)gr * OUTC + gc;
                if constexpr (MODE == 0) {
                    v0 += b0; v1 += b1;
                    *(float2*)(g_inp + o) = make_float2(v0, v1);
                    __nv_bfloat162 h2 =
                        __floats2bfloat162_rn(fmaxf(v0, 0.f), fmaxf(v1, 0.f));
                    *(__nv_bfloat162*)(outb + o) = h2;
                } else if constexpr (MODE == 1) {
                    v0 += b0; v1 += b1;
                    float2 rin = *(const float2*)(g_inp + o);
                    __nv_bfloat162 h2 = __floats2bfloat162_rn(
                        fmaxf(v0, 0.f) + 0.2f * rin.x, fmaxf(v1, 0.f) + 0.2f * rin.y);
                    *(__nv_bfloat162*)(outb + o) = h2;
                } else {
                    *(float2*)(g_aggf + o) = make_float2(v0, v1);   // p (fp32)
                    float q0 = acc2[mt][nt][half * 2] + b0;
                    float q1 = acc2[mt][nt][half * 2 + 1] + b1;
                    *(float2*)(outExt + o) = make_float2(q0, q1);
                }
            }
        }
    }
}

// ---------------- final: mean-agg of p (64-dim fp32) + q, fused log_softmax ------------
__global__ void __launch_bounds__(256) k_agg64_lsm(float* __restrict__ out) {
    int w = (blockIdx.x * blockDim.x + threadIdx.x) >> 5;
    if (w >= NNODE) return;
    const float* __restrict__ p = g_aggf;
    int lane = threadIdx.x & 31;
    int beg = g_rowptr[w], end = g_rowptr[w + 1];
    float ax = 0.f, ay = 0.f;
    int i = beg;
    for (; i + 3 < end; i += 4) {
        int s0 = g_col[i], s1 = g_col[i + 1], s2 = g_col[i + 2], s3 = g_col[i + 3];
        float2 a = __ldg((const float2*)(p + (size_t)s0 * 64 + lane * 2));
        float2 b = __ldg((const float2*)(p + (size_t)s1 * 64 + lane * 2));
        float2 cc = __ldg((const float2*)(p + (size_t)s2 * 64 + lane * 2));
        float2 d = __ldg((const float2*)(p + (size_t)s3 * 64 + lane * 2));
        ax += (a.x + b.x) + (cc.x + d.x);
        ay += (a.y + b.y) + (cc.y + d.y);
    }
    for (; i < end; i++) {
        int s0 = g_col[i];
        float2 a = __ldg((const float2*)(p + (size_t)s0 * 64 + lane * 2));
        ax += a.x; ay += a.y;
    }
    float d = g_deginv[w];
    float2 q = *(float2*)(out + (size_t)w * 64 + lane * 2);
    float v0 = q.x + ax * d;
    float v1 = q.y + ay * d;
    float m = fmaxf(v0, v1);
#pragma unroll
    for (int s = 16; s; s >>= 1) m = fmaxf(m, __shfl_xor_sync(0xffffffffu, m, s));
    float e = expf(v0 - m) + expf(v1 - m);
#pragma unroll
    for (int s = 16; s; s >>= 1) e += __shfl_xor_sync(0xffffffffu, e, s);
    float l = m + logf(e);
    *(float2*)(out + (size_t)w * 64 + lane * 2) = make_float2(v0 - l, v1 - l);
}

// ---------------- launcher (kernel launches + event fork/join — graph-capture safe) ----
extern "C" void kernel_launch(void* const* d_in, const int* in_sizes, int n_in,
                              void* d_out, int out_size) {
    const float* x    = (const float*)d_in[0];
    const int*   ei   = (const int*)d_in[1];     // int32 (JAX demotes int64)
    const float* w_in = (const float*)d_in[2];
    const float* b_in = (const float*)d_in[3];
    const float* w_l0 = (const float*)d_in[4];
    const float* w_r0 = (const float*)d_in[5];
    const float* b0   = (const float*)d_in[6];
    const float* w_l1 = (const float*)d_in[7];
    const float* w_r1 = (const float*)d_in[8];
    const float* b1   = (const float*)d_in[9];
    const float* w_l2 = (const float*)d_in[10];
    const float* w_r2 = (const float*)d_in[11];
    const float* b2   = (const float*)d_in[12];
    float* out = (float*)d_out;

    const int GB128 = (NNODE + 127) / 128;           // 391
    const int EDGE4_BLOCKS = (NEDGE / 4 + 255) / 256;
    const int WARP_BLOCKS = (NNODE * 32 + 255) / 256;
    const int SCAN_BLOCKS = (NNODE + 1023) / 1024;   // 49

    const int W_IN = 0, W_L0 = 8192, W_R0 = 16384, W_L1 = 24576, W_R1 = 32768;
    const int W_L2 = 40960, W_R2 = 45056;

    // one-time host-side resources (created on the FIRST call, which is NOT captured)
    static cudaStream_t sCsr = nullptr;
    static cudaEvent_t evFork = nullptr, evJoin = nullptr;
    if (!sCsr) {
        cudaStreamCreateWithFlags(&sCsr, cudaStreamNonBlocking);
        cudaEventCreateWithFlags(&evFork, cudaEventDisableTiming);
        cudaEventCreateWithFlags(&evJoin, cudaEventDisableTiming);
    }

    // ---- fork: CSR branch runs concurrently with wconv + embedding GEMM ----
    cudaEventRecord(evFork, 0);
    cudaStreamWaitEvent(sCsr, evFork, 0);

    // CSR branch (stream sCsr)
    k_zero_fill<<<(NNODE + 255) / 256, 256, 0, sCsr>>>();
    k_hist<<<EDGE4_BLOCKS, 256, 0, sCsr>>>(ei);
    k_scan1<<<SCAN_BLOCKS, 1024, 0, sCsr>>>();
    k_scan3<<<SCAN_BLOCKS, 1024, 0, sCsr>>>();
    k_csr_fill<<<EDGE4_BLOCKS, 256, 0, sCsr>>>(ei);
    cudaEventRecord(evJoin, sCsr);

    // main branch (capture stream): weights + input embedding
    k_wconv<<<192, 256>>>(w_in, w_l0, w_r0, w_l1, w_r1, w_l2, w_r2);
    k_mma<128, 0><<<GB128, 256>>>(x, W_IN, 0, b_in, nullptr, 0);

    // ---- join: aggregation needs both CSR and embedding ----
    cudaStreamWaitEvent(0, evJoin, 0);

    // layer 0: agg(bufA) -> gemm -> bufB
    k_agg<<<WARP_BLOCKS, 256>>>(0);
    k_mma<128, 1><<<GB128, 256>>>(nullptr, W_L0, W_R0, b0, nullptr, 0);
    // layer 1: agg(bufB) -> gemm -> bufA
    k_agg<<<WARP_BLOCKS, 256>>>(1);
    k_mma<128, 1><<<GB128, 256>>>(nullptr, W_L1, W_R1, b1, nullptr, 1);
    // layer 2: p = bufA@w_l2 -> g_aggf; q = bufA@w_r2 + b2 -> out
    k_mma<64, 2><<<GB128, 256>>>(nullptr, W_L2, W_R2, b2, out, 0);
    // out = log_softmax(q + mean_agg(p))
    k_agg64_lsm<<<WARP_BLOCKS, 256>>>(out);
}